// round 1
// baseline (speedup 1.0000x reference)
#include <cuda_runtime.h>

#define BATCH 4
#define SEQ 2048
#define DIM 1024
#define HEADS 16
#define DHEAD 64
#define INNER 1024
#define TOKENS (BATCH * SEQ)
#define ATT_SCALE 0.125f

// Scratch (allocation-free): q, k, v, attention output. 32 MB each.
__device__ float g_q[TOKENS * INNER];
__device__ float g_k[TOKENS * INNER];
__device__ float g_v[TOKENS * INNER];
__device__ float g_o[TOKENS * INNER];

// ---------------------------------------------------------------------------
// Tiled fp32 GEMM: C = A[M,K] @ B[K,N] (+bias). Output columns < splitN go to
// C0 (ld = splitN), columns >= splitN go to C1 (ld = N - splitN).
// BM=BN=128, BK=16, 256 threads, 8x8 microtile per thread.
// All problem dims here are multiples of the tiles -> no bounds checks.
// ---------------------------------------------------------------------------
#define GBM 128
#define GBN 128
#define GBK 16

__global__ __launch_bounds__(256, 2)
void gemm_kernel(const float* __restrict__ A, const float* __restrict__ B,
                 float* __restrict__ C0, float* __restrict__ C1,
                 int splitN, const float* __restrict__ bias,
                 int N, int K)
{
    __shared__ float As[GBK][GBM];   // A tile, transposed: As[k][m]
    __shared__ float Bs[GBK][GBN];   // B tile, natural:    Bs[k][n]

    const int m0  = blockIdx.y * GBM;
    const int n0  = blockIdx.x * GBN;
    const int tid = threadIdx.x;
    const int ty  = tid >> 4;        // 0..15 -> row group
    const int tx  = tid & 15;        // 0..15 -> col group

    // A-tile load mapping: 2 float4 per thread
    const int arow = tid >> 2;           // 0..63
    const int acol = (tid & 3) << 2;     // 0,4,8,12
    // B-tile load mapping: 2 float4 per thread (fully coalesced)
    const int brow = tid >> 5;           // 0..7
    const int bcol = (tid & 31) << 2;    // 0..124

    const float* Ap = A + m0 * K;
    const float* Bp = B + n0;

    float acc[8][8];
#pragma unroll
    for (int i = 0; i < 8; i++)
#pragma unroll
        for (int j = 0; j < 8; j++) acc[i][j] = 0.f;

    for (int k0 = 0; k0 < K; k0 += GBK) {
        float4 a0 = *(const float4*)(Ap + arow * K + k0 + acol);
        float4 a1 = *(const float4*)(Ap + (arow + 64) * K + k0 + acol);
        float4 b0 = *(const float4*)(Bp + (k0 + brow) * N + bcol);
        float4 b1 = *(const float4*)(Bp + (k0 + brow + 8) * N + bcol);
        __syncthreads();   // previous iteration's smem reads done
        As[acol + 0][arow] = a0.x;
        As[acol + 1][arow] = a0.y;
        As[acol + 2][arow] = a0.z;
        As[acol + 3][arow] = a0.w;
        As[acol + 0][arow + 64] = a1.x;
        As[acol + 1][arow + 64] = a1.y;
        As[acol + 2][arow + 64] = a1.z;
        As[acol + 3][arow + 64] = a1.w;
        *(float4*)&Bs[brow][bcol]     = b0;
        *(float4*)&Bs[brow + 8][bcol] = b1;
        __syncthreads();

#pragma unroll
        for (int k = 0; k < GBK; k++) {
            float av[8], bv[8];
            *(float4*)&av[0] = *(const float4*)&As[k][ty * 8];
            *(float4*)&av[4] = *(const float4*)&As[k][ty * 8 + 4];
            *(float4*)&bv[0] = *(const float4*)&Bs[k][tx * 8];
            *(float4*)&bv[4] = *(const float4*)&Bs[k][tx * 8 + 4];
#pragma unroll
            for (int i = 0; i < 8; i++)
#pragma unroll
                for (int j = 0; j < 8; j++)
                    acc[i][j] = fmaf(av[i], bv[j], acc[i][j]);
        }
    }

    // Epilogue: whole 128-wide block lands on one side of the split
    float* Cb;
    int ldc, c0;
    if (n0 < splitN) { Cb = C0; ldc = splitN;     c0 = n0; }
    else             { Cb = C1; ldc = N - splitN; c0 = n0 - splitN; }

#pragma unroll
    for (int i = 0; i < 8; i++) {
        int row = m0 + ty * 8 + i;
#pragma unroll
        for (int j = 0; j < 8; j += 4) {
            float4 r;
            r.x = acc[i][j];     r.y = acc[i][j + 1];
            r.z = acc[i][j + 2]; r.w = acc[i][j + 3];
            if (bias) {
                int gc = n0 + tx * 8 + j;
                r.x += bias[gc];     r.y += bias[gc + 1];
                r.z += bias[gc + 2]; r.w += bias[gc + 3];
            }
            *(float4*)(Cb + row * ldc + c0 + tx * 8 + j) = r;
        }
    }
}

// ---------------------------------------------------------------------------
// Flash attention, fp32. One block = 64 query rows of one (batch, head).
// 256 threads as a 16x16 grid; each thread owns a 4x4 microtile of the 64x64
// S tile and a 4x4 microtile (rows x dims) of the 64x64 O accumulator.
// Smem: Qs (Q^T, swizzled), KPs (K^T swizzled, reused for P^T swizzled),
// Vs (natural). 3 x 16 KB = 48 KB static.
// Swizzle: element (r, c) of a logically-transposed [64][64] tile lives at
// physical column ((c>>2) ^ (r>>2))*4 + (c&3)  -> all compute-phase vector
// LDS are conflict-free; transpose stores are ~2-4 way instead of 16-way.
// ---------------------------------------------------------------------------
__global__ __launch_bounds__(256, 2)
void flash_kernel(const float* __restrict__ Q, const float* __restrict__ Kg,
                  const float* __restrict__ Vg, float* __restrict__ O)
{
    __shared__ float Qs[64][64];    // Q^T : [d][row] swizzled
    __shared__ float KPs[64][64];   // K^T : [d][col] swizzled, then P^T : [col][row]
    __shared__ float Vs[64][64];    // V   : [col][d] natural

    const int bh  = blockIdx.y;
    const int b   = bh >> 4;
    const int h   = bh & 15;
    const int qt  = blockIdx.x;
    const int tid = threadIdx.x;
    const int ty  = tid >> 4;   // row group (S rows & O rows)
    const int tx  = tid & 15;   // col group (S cols / O dims)

    const float* qb = Q  + (b * SEQ + qt * 64) * INNER + h * DHEAD;
    const float* kb = Kg + b * SEQ * INNER + h * DHEAD;
    const float* vb = Vg + b * SEQ * INNER + h * DHEAD;

    // Load Q tile transposed + swizzled
#pragma unroll
    for (int rep = 0; rep < 4; rep++) {
        int f   = tid + rep * 256;
        int row = f >> 4;
        int d4  = f & 15;
        float4 v = *(const float4*)(qb + row * INNER + d4 * 4);
        int pc = (((row >> 2) ^ d4) << 2) + (row & 3);
        Qs[d4 * 4 + 0][pc] = v.x;
        Qs[d4 * 4 + 1][pc] = v.y;
        Qs[d4 * 4 + 2][pc] = v.z;
        Qs[d4 * 4 + 3][pc] = v.w;
    }

    float acc[4][4];
    float m[4], l[4];
#pragma unroll
    for (int i = 0; i < 4; i++) {
        m[i] = -1e30f; l[i] = 0.f;
#pragma unroll
        for (int j = 0; j < 4; j++) acc[i][j] = 0.f;
    }

    for (int kb0 = 0; kb0 < SEQ / 64; kb0++) {
        __syncthreads();   // previous iteration's P/V reads done
        const float* kp = kb + kb0 * 64 * INNER;
        const float* vp = vb + kb0 * 64 * INNER;
#pragma unroll
        for (int rep = 0; rep < 4; rep++) {
            int f   = tid + rep * 256;
            int row = f >> 4;
            int d4  = f & 15;
            float4 kv = *(const float4*)(kp + row * INNER + d4 * 4);
            int pc = (((row >> 2) ^ d4) << 2) + (row & 3);
            KPs[d4 * 4 + 0][pc] = kv.x;
            KPs[d4 * 4 + 1][pc] = kv.y;
            KPs[d4 * 4 + 2][pc] = kv.z;
            KPs[d4 * 4 + 3][pc] = kv.w;
            float4 vv = *(const float4*)(vp + row * INNER + d4 * 4);
            *(float4*)&Vs[row][d4 * 4] = vv;
        }
        __syncthreads();

        // S = Q @ K^T (4x4 per thread)
        float s[4][4];
#pragma unroll
        for (int i = 0; i < 4; i++)
#pragma unroll
            for (int j = 0; j < 4; j++) s[i][j] = 0.f;
#pragma unroll 8
        for (int kd = 0; kd < 64; kd++) {
            float4 a = *(const float4*)&Qs[kd][(ty ^ (kd >> 2)) << 2];
            float4 c = *(const float4*)&KPs[kd][(tx ^ (kd >> 2)) << 2];
            float av[4] = {a.x, a.y, a.z, a.w};
            float cv[4] = {c.x, c.y, c.z, c.w};
#pragma unroll
            for (int i = 0; i < 4; i++)
#pragma unroll
                for (int j = 0; j < 4; j++)
                    s[i][j] = fmaf(av[i], cv[j], s[i][j]);
        }

        // Online softmax (row stats reduced over the 16 lanes sharing a row)
        float p[4][4];
#pragma unroll
        for (int i = 0; i < 4; i++) {
            float rm = -1e30f;
#pragma unroll
            for (int j = 0; j < 4; j++) {
                s[i][j] *= ATT_SCALE;
                rm = fmaxf(rm, s[i][j]);
            }
            rm = fmaxf(rm, __shfl_xor_sync(0xffffffffu, rm, 8));
            rm = fmaxf(rm, __shfl_xor_sync(0xffffffffu, rm, 4));
            rm = fmaxf(rm, __shfl_xor_sync(0xffffffffu, rm, 2));
            rm = fmaxf(rm, __shfl_xor_sync(0xffffffffu, rm, 1));
            float mn    = fmaxf(m[i], rm);
            float alpha = __expf(m[i] - mn);
            m[i] = mn;
            float rs = 0.f;
#pragma unroll
            for (int j = 0; j < 4; j++) {
                p[i][j] = __expf(s[i][j] - mn);
                rs += p[i][j];
            }
            rs += __shfl_xor_sync(0xffffffffu, rs, 8);
            rs += __shfl_xor_sync(0xffffffffu, rs, 4);
            rs += __shfl_xor_sync(0xffffffffu, rs, 2);
            rs += __shfl_xor_sync(0xffffffffu, rs, 1);
            l[i] = l[i] * alpha + rs;
#pragma unroll
            for (int j = 0; j < 4; j++) acc[i][j] *= alpha;
        }

        __syncthreads();   // done reading KPs as K
        // Store P^T swizzled into KPs: logical (row = col tx*4+jj, col = ty*4+ii)
#pragma unroll
        for (int jj = 0; jj < 4; jj++) {
            int prow = tx * 4 + jj;
            int pcol = (ty ^ tx) << 2;
#pragma unroll
            for (int ii = 0; ii < 4; ii++)
                KPs[prow][pcol + ii] = p[ii][jj];
        }
        __syncthreads();

        // O += P @ V
#pragma unroll 8
        for (int j = 0; j < 64; j++) {
            float4 pv = *(const float4*)&KPs[j][(ty ^ (j >> 2)) << 2];
            float4 vv = *(const float4*)&Vs[j][tx * 4];
            float pa[4] = {pv.x, pv.y, pv.z, pv.w};
            float va[4] = {vv.x, vv.y, vv.z, vv.w};
#pragma unroll
            for (int i = 0; i < 4; i++)
#pragma unroll
                for (int jd = 0; jd < 4; jd++)
                    acc[i][jd] = fmaf(pa[i], va[jd], acc[i][jd]);
        }
    }

    // Normalize and write O in [b, n, h*d] layout (ready for out-proj GEMM)
    float* ob = O + (b * SEQ + qt * 64) * INNER + h * DHEAD;
#pragma unroll
    for (int i = 0; i < 4; i++) {
        float inv = 1.f / l[i];
        int row = ty * 4 + i;
        float4 r;
        r.x = acc[i][0] * inv; r.y = acc[i][1] * inv;
        r.z = acc[i][2] * inv; r.w = acc[i][3] * inv;
        *(float4*)(ob + row * INNER + tx * 4) = r;
    }
}

// ---------------------------------------------------------------------------
extern "C" void kernel_launch(void* const* d_in, const int* in_sizes, int n_in,
                              void* d_out, int out_size)
{
    const float* x   = (const float*)d_in[0];
    const float* Wq  = (const float*)d_in[1];
    const float* Wkv = (const float*)d_in[2];
    const float* Wo  = (const float*)d_in[3];
    const float* bo  = (const float*)d_in[4];
    float* out = (float*)d_out;

    float *q, *k, *v, *o;
    cudaGetSymbolAddress((void**)&q, g_q);
    cudaGetSymbolAddress((void**)&k, g_k);
    cudaGetSymbolAddress((void**)&v, g_v);
    cudaGetSymbolAddress((void**)&o, g_o);

    dim3 blk(256);

    // q = x @ Wq                          [8192,1024] x [1024,1024]
    gemm_kernel<<<dim3(INNER / GBN, TOKENS / GBM), blk>>>(
        x, Wq, q, nullptr, INNER, nullptr, INNER, DIM);

    // [k | v] = x @ Wkv                   [8192,1024] x [1024,2048], split epilogue
    gemm_kernel<<<dim3(2 * INNER / GBN, TOKENS / GBM), blk>>>(
        x, Wkv, k, v, INNER, nullptr, 2 * INNER, DIM);

    // o = softmax(q k^T * scale) v        per (batch, head)
    flash_kernel<<<dim3(SEQ / 64, BATCH * HEADS), blk>>>(q, k, v, o);

    // out = o @ Wo + bo                   [8192,1024] x [1024,1024]
    gemm_kernel<<<dim3(DIM / GBN, TOKENS / GBM), blk>>>(
        o, Wo, out, nullptr, DIM, bo, DIM, DIM);
}